// round 15
// baseline (speedup 1.0000x reference)
#include <cuda_runtime.h>
#include <cstdint>

// ---------------- static scratch (device globals: allocation-free) ----------------
#define NMAX 100000
#define EMAX 1600000
#define HDIM 64

__device__ float g_deg[NMAX];
__device__ float g_dis[NMAX];
__device__ int   g_src[EMAX];
__device__ int   g_tgt[EMAX];
__device__ int   g_rowcnt[NMAX];
__device__ int   g_rowptr[NMAX + 1];
__device__ int   g_cursor[NMAX];
__device__ int   g_bsum[128];
__device__ int   g_bsumoff[128];
__device__ int2  g_epay[EMAX];          // {src, bits(wn)} grouped by tgt
__device__ float g_bufA[(size_t)NMAX * HDIM];
__device__ float g_bufB[(size_t)NMAX * HDIM];
__device__ float g_tx1[(size_t)NMAX * HDIM];
__device__ float g_tmp[(size_t)NMAX * HDIM];
__device__ float g_weff[4 * 192 * 64];
__device__ float g_sums[64];
__device__ float g_cnt[64];

// ---------------- utility ----------------
__global__ void init_counts_kernel(int n) {
    int i = blockIdx.x * blockDim.x + threadIdx.x;
    if (i < n) { g_deg[i] = 0.f; g_rowcnt[i] = 0; }
}

// ---------------- preprocessing ----------------
__global__ void edge_prep_kernel(const int* __restrict__ ei,
                                 const float* __restrict__ ew, int E, int N) {
    int e = blockIdx.x * blockDim.x + threadIdx.x;
    if (e >= E) return;
    int s = ei[e];
    int t = ei[(size_t)E + e];
    if ((unsigned)s >= (unsigned)N) s = 0;
    if ((unsigned)t >= (unsigned)N) t = 0;
    g_src[e] = s;
    g_tgt[e] = t;
    atomicAdd(&g_deg[s], ew[e]);
    atomicAdd(&g_rowcnt[t], 1);
}

// ---- multi-block exclusive scan of g_rowcnt -> g_rowptr (+ dis fused) ----
__global__ void scan_block_kernel(int N) {
    __shared__ int wsum[32];
    int tid = threadIdx.x, lane = tid & 31, wid = tid >> 5;
    int i = blockIdx.x * 1024 + tid;
    if (i < N) {
        float d = g_deg[i];
        g_dis[i] = (d > 0.f) ? rsqrtf(d) : 0.f;
    }
    int v = (i < N) ? g_rowcnt[i] : 0;
    int s = v;
#pragma unroll
    for (int o = 1; o < 32; o <<= 1) {
        int u = __shfl_up_sync(0xffffffffu, s, o);
        if (lane >= o) s += u;
    }
    if (lane == 31) wsum[wid] = s;
    __syncthreads();
    if (tid < 32) {
        int s2 = wsum[tid];
#pragma unroll
        for (int o = 1; o < 32; o <<= 1) {
            int u = __shfl_up_sync(0xffffffffu, s2, o);
            if (tid >= o) s2 += u;
        }
        wsum[tid] = s2;
    }
    __syncthreads();
    int excl = (wid ? wsum[wid - 1] : 0) + (s - v);
    if (i < N) g_rowptr[i] = excl;
    if (tid == 1023) g_bsum[blockIdx.x] = wsum[31];
}

__global__ void scan_bsum_kernel(int nb) {
    __shared__ int ws[4];
    int tid = threadIdx.x, lane = tid & 31, wid = tid >> 5;
    int v = (tid < nb) ? g_bsum[tid] : 0;
    int s = v;
#pragma unroll
    for (int o = 1; o < 32; o <<= 1) {
        int u = __shfl_up_sync(0xffffffffu, s, o);
        if (lane >= o) s += u;
    }
    if (lane == 31) ws[wid] = s;
    __syncthreads();
    if (tid == 0) { int a = 0; for (int w = 0; w < 4; w++) { int t = ws[w]; ws[w] = a; a += t; } }
    __syncthreads();
    int excl = ws[wid] + (s - v);
    if (tid < nb) g_bsumoff[tid] = excl;
}

__global__ void scan_add_kernel(int N, int E) {
    int i = blockIdx.x * 1024 + threadIdx.x;
    if (i < N) {
        int r = g_rowptr[i] + g_bsumoff[blockIdx.x];
        g_rowptr[i] = r;
        g_cursor[i] = r;
    }
    if (blockIdx.x == 0 && threadIdx.x == 0) g_rowptr[N] = E;
}

__global__ void fill_kernel(const float* __restrict__ ew, int E) {
    int e = blockIdx.x * blockDim.x + threadIdx.x;
    if (e >= E) return;
    int s = g_src[e];
    int t = g_tgt[e];
    float wn = -g_dis[s] * ew[e] * g_dis[t];
    int pos = atomicAdd(&g_cursor[t], 1);
    g_epay[pos] = make_int2(s, __float_as_int(wn));
}

// Weff[l][kk][o]: kk<64 -> W0-W2 ; 64..127 -> W1 ; 128..191 -> 2*W2
// (also zeroes the pooling accumulators: one launch fewer)
__global__ void weff_kernel(const float* __restrict__ w) {
    int idx = blockIdx.x * blockDim.x + threadIdx.x;
    if (blockIdx.x == 0) {
        if (threadIdx.x < 64) g_sums[threadIdx.x] = 0.f;
        else if (threadIdx.x < 128) g_cnt[threadIdx.x - 64] = 0.f;
    }
    if (idx >= 4 * 192 * 64) return;
    int o  = idx & 63;
    int kk = (idx >> 6) % 192;
    int l  = idx / (192 * 64);
    const float* wl = w + (size_t)l * 3 * 4096;
    float v;
    if (kk < 64)       v = wl[kk * 64 + o] - wl[2 * 4096 + kk * 64 + o];
    else if (kk < 128) v = wl[4096 + (kk - 64) * 64 + o];
    else               v = 2.f * wl[2 * 4096 + (kk - 128) * 64 + o];
    g_weff[idx] = v;
}

// ---------------- warp-per-node CSR propagation (pipelined payload batches) ----------------
__global__ void prop_warp_kernel(const float* __restrict__ h, float* __restrict__ out, int n) {
    int node = (blockIdx.x * blockDim.x + threadIdx.x) >> 5;
    if (node >= n) return;
    int lane = threadIdx.x & 31;
    int beg = g_rowptr[node];
    int end = g_rowptr[node + 1];
    const float2* __restrict__ hp = reinterpret_cast<const float2*>(h);
    float ax = 0.f, ay = 0.f;
    // prefetch first batch
    int jj = beg + lane;
    int2 p = (jj < end) ? g_epay[jj] : make_int2(0, 0);
    for (int j0 = beg; j0 < end; j0 += 32) {
        // prefetch next batch before consuming current
        int nj = j0 + 32 + lane;
        int2 pn = (nj < end) ? g_epay[nj] : make_int2(0, 0);
        int cnt = end - j0;
        if (cnt > 32) cnt = 32;
#pragma unroll 8
        for (int k = 0; k < cnt; k++) {
            int s   = __shfl_sync(0xffffffffu, p.x, k);
            float w = __int_as_float(__shfl_sync(0xffffffffu, p.y, k));
            float2 v = hp[(size_t)s * 32 + lane];
            ax += w * v.x;
            ay += w * v.y;
        }
        p = pn;
    }
    reinterpret_cast<float2*>(out)[(size_t)node * 32 + lane] = make_float2(ax, ay);
}

// ---------------- tensor-core GEMM: out = [p0|p1|p2] @ Weff + bias (3xTF32) ----------------
__device__ __forceinline__ uint32_t f2tf32(float x) {
    uint32_t r;
    asm("cvt.rna.tf32.f32 %0, %1;" : "=r"(r) : "f"(x));
    return r;
}

__device__ __forceinline__ void mma_tf32(float* d,
                                         uint32_t a0, uint32_t a1, uint32_t a2, uint32_t a3,
                                         uint32_t b0, uint32_t b1) {
    asm volatile("mma.sync.aligned.m16n8k8.row.col.f32.tf32.tf32.f32 "
                 "{%0,%1,%2,%3}, {%4,%5,%6,%7}, {%8,%9}, {%0,%1,%2,%3};"
                 : "+f"(d[0]), "+f"(d[1]), "+f"(d[2]), "+f"(d[3])
                 : "r"(a0), "r"(a1), "r"(a2), "r"(a3), "r"(b0), "r"(b1));
}

// BM=128, BN=64, K=192 (6 chunks of 32). 8 warps, 32x32 warp tiles.
// A and W pre-split into tf32 hi/lo at SMEM staging time -> inner loop is LDS+MMA only.
// Strides 136/72 (=8 mod 32) keep all LDS patterns conflict-free.
#define AHI(k, r) smem[(size_t)(k) * 136 + (r)]
#define ALO(k, r) smem[A_OFF + (size_t)(k) * 136 + (r)]
#define WHI(k, c) smem[W_OFF + (size_t)(k) * 72 + (c)]
#define WLO(k, c) smem[W_OFF + W2_OFF + (size_t)(k) * 72 + (c)]
#define A_OFF  (32 * 136)
#define W_OFF  (2 * 32 * 136)
#define W2_OFF (32 * 72)
#define GEMM_SMEM_BYTES ((2 * 32 * 136 + 2 * 32 * 72) * 4)

__global__ void __launch_bounds__(256, 2)
gemm_tc_kernel(const float* __restrict__ p0, const float* __restrict__ p1,
               const float* __restrict__ p2, const float* __restrict__ W,
               const float* __restrict__ bias, float* __restrict__ out, int N) {
    extern __shared__ float smem[];
    int tid = threadIdx.x;
    int lane = tid & 31;
    int wid = tid >> 5;               // 0..7
    int warp_m = wid >> 1;            // 0..3
    int warp_n = wid & 1;             // 0..1
    int gid = lane >> 2;              // 0..7
    int tig = lane & 3;               // 0..3
    int m0 = blockIdx.x * 128;

    float acc[2][4][4];
#pragma unroll
    for (int mf = 0; mf < 2; mf++)
#pragma unroll
        for (int nf = 0; nf < 4; nf++)
#pragma unroll
            for (int q = 0; q < 4; q++) acc[mf][nf][q] = 0.f;

    const float* parts[3] = {p0, p1, p2};

#pragma unroll 1
    for (int c = 0; c < 6; c++) {
        const float* P = parts[c >> 1];
        int kbase = (c & 1) * 32;
        // stage A chunk (128 rows x 32 k), split hi/lo once per element
#pragma unroll
        for (int i = 0; i < 4; i++) {
            int idx = i * 256 + tid;
            int row = idx & 127;
            int kq = idx >> 7;         // 0..7
            int grow = m0 + row;
            float4 v = make_float4(0.f, 0.f, 0.f, 0.f);
            if (grow < N)
                v = *reinterpret_cast<const float4*>(P + (size_t)grow * 64 + kbase + kq * 4);
            float vv[4] = {v.x, v.y, v.z, v.w};
#pragma unroll
            for (int q = 0; q < 4; q++) {
                uint32_t hb = f2tf32(vv[q]);
                AHI(kq * 4 + q, row) = __uint_as_float(hb);
                ALO(kq * 4 + q, row) = __uint_as_float(f2tf32(vv[q] - __uint_as_float(hb)));
            }
        }
        // stage W chunk (32 k-rows x 64 n), split hi/lo
#pragma unroll
        for (int i = 0; i < 8; i++) {
            int idx = i * 256 + tid;
            int k = idx >> 6;          // 0..31
            int n = idx & 63;
            float w = W[(size_t)(c * 32 + k) * 64 + n];
            uint32_t hb = f2tf32(w);
            WHI(k, n) = __uint_as_float(hb);
            WLO(k, n) = __uint_as_float(f2tf32(w - __uint_as_float(hb)));
        }
        __syncthreads();

#pragma unroll
        for (int ks = 0; ks < 4; ks++) {
            int k0 = ks * 8;
            uint32_t bh[4][2], bl[4][2];
#pragma unroll
            for (int nf = 0; nf < 4; nf++) {
                int col = warp_n * 32 + nf * 8 + gid;
                bh[nf][0] = __float_as_uint(WHI(k0 + tig, col));
                bh[nf][1] = __float_as_uint(WHI(k0 + tig + 4, col));
                bl[nf][0] = __float_as_uint(WLO(k0 + tig, col));
                bl[nf][1] = __float_as_uint(WLO(k0 + tig + 4, col));
            }
            uint32_t ah[2][4], al[2][4];
#pragma unroll
            for (int mf = 0; mf < 2; mf++) {
                int rb = warp_m * 32 + mf * 16;
                // PTX m16n8k8 A frag: a0=A[g][t], a1=A[g+8][t], a2=A[g][t+4], a3=A[g+8][t+4]
                ah[mf][0] = __float_as_uint(AHI(k0 + tig, rb + gid));
                ah[mf][1] = __float_as_uint(AHI(k0 + tig, rb + gid + 8));
                ah[mf][2] = __float_as_uint(AHI(k0 + tig + 4, rb + gid));
                ah[mf][3] = __float_as_uint(AHI(k0 + tig + 4, rb + gid + 8));
                al[mf][0] = __float_as_uint(ALO(k0 + tig, rb + gid));
                al[mf][1] = __float_as_uint(ALO(k0 + tig, rb + gid + 8));
                al[mf][2] = __float_as_uint(ALO(k0 + tig + 4, rb + gid));
                al[mf][3] = __float_as_uint(ALO(k0 + tig + 4, rb + gid + 8));
            }
#pragma unroll
            for (int mf = 0; mf < 2; mf++)
#pragma unroll
                for (int nf = 0; nf < 4; nf++) {
                    mma_tf32(acc[mf][nf], ah[mf][0], ah[mf][1], ah[mf][2], ah[mf][3],
                             bh[nf][0], bh[nf][1]);
                    mma_tf32(acc[mf][nf], ah[mf][0], ah[mf][1], ah[mf][2], ah[mf][3],
                             bl[nf][0], bl[nf][1]);
                    mma_tf32(acc[mf][nf], al[mf][0], al[mf][1], al[mf][2], al[mf][3],
                             bh[nf][0], bh[nf][1]);
                }
        }
        __syncthreads();
    }

    // epilogue: bias + store (C frag: c0=C[g][2t], c1=C[g][2t+1], c2=C[g+8][2t], c3=C[g+8][2t+1])
#pragma unroll
    for (int mf = 0; mf < 2; mf++) {
#pragma unroll
        for (int nf = 0; nf < 4; nf++) {
            int col = warp_n * 32 + nf * 8 + 2 * tig;
            float b0 = bias[col], b1 = bias[col + 1];
            int row0 = m0 + warp_m * 32 + mf * 16 + gid;
            if (row0 < N) {
                float2 o = make_float2(acc[mf][nf][0] + b0, acc[mf][nf][1] + b1);
                *reinterpret_cast<float2*>(out + (size_t)row0 * 64 + col) = o;
            }
            int row1 = row0 + 8;
            if (row1 < N) {
                float2 o = make_float2(acc[mf][nf][2] + b0, acc[mf][nf][3] + b1);
                *reinterpret_cast<float2*>(out + (size_t)row1 * 64 + col) = o;
            }
        }
    }
}

// ---------------- readout MLP (64->32 relu ->1) + scatter mean ----------------
__global__ void readout_kernel(const float* __restrict__ y, const int* __restrict__ batch,
                               const float* __restrict__ wr1, const float* __restrict__ br1,
                               const float* __restrict__ wr2, const float* __restrict__ br2,
                               int n, int G) {
    __shared__ float Wsm[64 * 32];
    __shared__ float w2sm[32];
    __shared__ float b1sm[32];
    for (int i = threadIdx.x; i < 64 * 32; i += blockDim.x) Wsm[i] = wr1[i];
    if (threadIdx.x < 32) {
        w2sm[threadIdx.x] = wr2[threadIdx.x];
        b1sm[threadIdx.x] = br1[threadIdx.x];
    }
    __syncthreads();
    float b2 = br2[0];
    int lane = threadIdx.x & 31;
    int warp = (blockIdx.x * blockDim.x + threadIdx.x) >> 5;
    int nwarps = (gridDim.x * blockDim.x) >> 5;
    for (int node = warp; node < n; node += nwarps) {
        float yv0 = y[(size_t)node * 64 + lane];
        float yv1 = y[(size_t)node * 64 + 32 + lane];
        float acc = b1sm[lane];
#pragma unroll
        for (int k = 0; k < 32; k++)
            acc += __shfl_sync(0xffffffffu, yv0, k) * Wsm[k * 32 + lane];
#pragma unroll
        for (int k = 0; k < 32; k++)
            acc += __shfl_sync(0xffffffffu, yv1, k) * Wsm[(32 + k) * 32 + lane];
        acc = fmaxf(acc, 0.f);
        float r = acc * w2sm[lane];
#pragma unroll
        for (int off = 16; off; off >>= 1)
            r += __shfl_xor_sync(0xffffffffu, r, off);
        if (lane == 0) {
            int g = batch[node];
            if ((unsigned)g < (unsigned)G) {
                atomicAdd(&g_sums[g], r + b2);
                atomicAdd(&g_cnt[g], 1.f);
            }
        }
    }
}

__global__ void finalize_kernel(float* __restrict__ out, int G) {
    int g = threadIdx.x;
    if (g < G) out[g] = g_sums[g] / fmaxf(g_cnt[g], 1.f);
}

// ---------------- host ----------------
extern "C" void kernel_launch(void* const* d_in, const int* in_sizes, int n_in,
                              void* d_out, int out_size) {
    const float* x        = (const float*)d_in[0];
    const int*   ei       = (const int*)d_in[1];     // int32 (JAX x64 disabled)
    const float* ew       = (const float*)d_in[2];
    const int*   batch    = (const int*)d_in[3];     // int32
    const float* w_layers = (const float*)d_in[4];
    const float* b_layers = (const float*)d_in[5];
    const float* wr1      = (const float*)d_in[6];
    const float* br1      = (const float*)d_in[7];
    const float* wr2      = (const float*)d_in[8];
    const float* br2      = (const float*)d_in[9];

    int N = in_sizes[0] / HDIM;
    int E = in_sizes[1] / 2;
    int G = out_size;

    float *bufA, *bufB, *tx1, *tmp, *weff;
    cudaGetSymbolAddress((void**)&bufA, g_bufA);
    cudaGetSymbolAddress((void**)&bufB, g_bufB);
    cudaGetSymbolAddress((void**)&tx1,  g_tx1);
    cudaGetSymbolAddress((void**)&tmp,  g_tmp);
    cudaGetSymbolAddress((void**)&weff, g_weff);

    static bool attr_set = false;
    if (!attr_set) {
        cudaFuncSetAttribute(gemm_tc_kernel,
                             cudaFuncAttributeMaxDynamicSharedMemorySize, GEMM_SMEM_BYTES);
        attr_set = true;
    }

    const int TPB = 256;
    int nb = (N + 1023) / 1024;

    // preprocessing: degrees + CSR by target + Weff (+ pool zero)
    init_counts_kernel<<<(N + TPB - 1) / TPB, TPB>>>(N);
    edge_prep_kernel<<<(E + TPB - 1) / TPB, TPB>>>(ei, ew, E, N);
    scan_block_kernel<<<nb, 1024>>>(N);
    scan_bsum_kernel<<<1, 128>>>(nb);
    scan_add_kernel<<<nb, 1024>>>(N, E);
    fill_kernel<<<(E + TPB - 1) / TPB, TPB>>>(ew, E);
    weff_kernel<<<(4 * 192 * 64 + TPB - 1) / TPB, TPB>>>(w_layers);

    int pgrid = (int)(((long long)N * 32 + TPB - 1) / TPB);
    int ggrid = (N + 127) / 128;

    const float* ycur = x;
    float* bufs[2] = {bufA, bufB};
    for (int l = 0; l < 4; l++) {
        prop_warp_kernel<<<pgrid, TPB>>>(ycur, tx1, N);
        prop_warp_kernel<<<pgrid, TPB>>>(tx1, tmp, N);
        gemm_tc_kernel<<<ggrid, TPB, GEMM_SMEM_BYTES>>>(ycur, tx1, tmp,
                                                        weff + (size_t)l * 192 * 64,
                                                        b_layers + (size_t)l * 64,
                                                        bufs[l & 1], N);
        ycur = bufs[l & 1];
    }

    // readout + pooling
    readout_kernel<<<256, TPB>>>(ycur, batch, wr1, br1, wr2, br2, N, G);
    finalize_kernel<<<1, 64>>>((float*)d_out, G);
}

// round 16
// speedup vs baseline: 1.0655x; 1.0655x over previous
#include <cuda_runtime.h>
#include <cuda_fp16.h>
#include <cstdint>

// ---------------- static scratch (device globals: allocation-free) ----------------
#define NMAX 100000
#define EMAX 1600000
#define HDIM 64

__device__ float  g_deg[NMAX];
__device__ float  g_dis[NMAX];
__device__ int    g_src[EMAX];
__device__ int    g_tgt[EMAX];
__device__ int    g_rowcnt[NMAX];
__device__ int    g_rowptr[NMAX + 1];
__device__ int    g_cursor[NMAX];
__device__ int    g_bsum[128];
__device__ int    g_bsumoff[128];
__device__ int2   g_epay[EMAX];          // {src, bits(wn)} grouped by tgt
__device__ float  g_bufA[(size_t)NMAX * HDIM];
__device__ float  g_bufB[(size_t)NMAX * HDIM];
__device__ float  g_tx1[(size_t)NMAX * HDIM];
__device__ float  g_tmp[(size_t)NMAX * HDIM];
__device__ __half2 g_hy16[(size_t)NMAX * 32];   // fp16 mirror of current layer input y
__device__ __half2 g_ht16[(size_t)NMAX * 32];   // fp16 mirror of tx1
__device__ float  g_weff[4 * 192 * 64];
__device__ float  g_sums[64];
__device__ float  g_cnt[64];

// ---------------- utility ----------------
__global__ void init_counts_kernel(int n) {
    int i = blockIdx.x * blockDim.x + threadIdx.x;
    if (i < n) { g_deg[i] = 0.f; g_rowcnt[i] = 0; }
}

// fp32 -> fp16 mirror (for the initial x)
__global__ void cvt16_kernel(const float* __restrict__ x, __half2* __restrict__ o, int n32) {
    int i = blockIdx.x * blockDim.x + threadIdx.x;
    if (i < n32) {
        float2 v = reinterpret_cast<const float2*>(x)[i];
        o[i] = __floats2half2_rn(v.x, v.y);
    }
}

// ---------------- preprocessing ----------------
__global__ void edge_prep_kernel(const int* __restrict__ ei,
                                 const float* __restrict__ ew, int E, int N) {
    int e = blockIdx.x * blockDim.x + threadIdx.x;
    if (e >= E) return;
    int s = ei[e];
    int t = ei[(size_t)E + e];
    if ((unsigned)s >= (unsigned)N) s = 0;
    if ((unsigned)t >= (unsigned)N) t = 0;
    g_src[e] = s;
    g_tgt[e] = t;
    atomicAdd(&g_deg[s], ew[e]);
    atomicAdd(&g_rowcnt[t], 1);
}

// ---- multi-block exclusive scan of g_rowcnt -> g_rowptr (+ dis fused) ----
__global__ void scan_block_kernel(int N) {
    __shared__ int wsum[32];
    int tid = threadIdx.x, lane = tid & 31, wid = tid >> 5;
    int i = blockIdx.x * 1024 + tid;
    if (i < N) {
        float d = g_deg[i];
        g_dis[i] = (d > 0.f) ? rsqrtf(d) : 0.f;
    }
    int v = (i < N) ? g_rowcnt[i] : 0;
    int s = v;
#pragma unroll
    for (int o = 1; o < 32; o <<= 1) {
        int u = __shfl_up_sync(0xffffffffu, s, o);
        if (lane >= o) s += u;
    }
    if (lane == 31) wsum[wid] = s;
    __syncthreads();
    if (tid < 32) {
        int s2 = wsum[tid];
#pragma unroll
        for (int o = 1; o < 32; o <<= 1) {
            int u = __shfl_up_sync(0xffffffffu, s2, o);
            if (tid >= o) s2 += u;
        }
        wsum[tid] = s2;
    }
    __syncthreads();
    int excl = (wid ? wsum[wid - 1] : 0) + (s - v);
    if (i < N) g_rowptr[i] = excl;
    if (tid == 1023) g_bsum[blockIdx.x] = wsum[31];
}

__global__ void scan_bsum_kernel(int nb) {
    __shared__ int ws[4];
    int tid = threadIdx.x, lane = tid & 31, wid = tid >> 5;
    int v = (tid < nb) ? g_bsum[tid] : 0;
    int s = v;
#pragma unroll
    for (int o = 1; o < 32; o <<= 1) {
        int u = __shfl_up_sync(0xffffffffu, s, o);
        if (lane >= o) s += u;
    }
    if (lane == 31) ws[wid] = s;
    __syncthreads();
    if (tid == 0) { int a = 0; for (int w = 0; w < 4; w++) { int t = ws[w]; ws[w] = a; a += t; } }
    __syncthreads();
    int excl = ws[wid] + (s - v);
    if (tid < nb) g_bsumoff[tid] = excl;
}

__global__ void scan_add_kernel(int N, int E) {
    int i = blockIdx.x * 1024 + threadIdx.x;
    if (i < N) {
        int r = g_rowptr[i] + g_bsumoff[blockIdx.x];
        g_rowptr[i] = r;
        g_cursor[i] = r;
    }
    if (blockIdx.x == 0 && threadIdx.x == 0) g_rowptr[N] = E;
}

__global__ void fill_kernel(const float* __restrict__ ew, int E) {
    int e = blockIdx.x * blockDim.x + threadIdx.x;
    if (e >= E) return;
    int s = g_src[e];
    int t = g_tgt[e];
    float wn = -g_dis[s] * ew[e] * g_dis[t];
    int pos = atomicAdd(&g_cursor[t], 1);
    g_epay[pos] = make_int2(s, __float_as_int(wn));
}

// Weff[l][kk][o]: kk<64 -> W0-W2 ; 64..127 -> W1 ; 128..191 -> 2*W2
// (also zeroes the pooling accumulators: one launch fewer)
__global__ void weff_kernel(const float* __restrict__ w) {
    int idx = blockIdx.x * blockDim.x + threadIdx.x;
    if (blockIdx.x == 0) {
        if (threadIdx.x < 64) g_sums[threadIdx.x] = 0.f;
        else if (threadIdx.x < 128) g_cnt[threadIdx.x - 64] = 0.f;
    }
    if (idx >= 4 * 192 * 64) return;
    int o  = idx & 63;
    int kk = (idx >> 6) % 192;
    int l  = idx / (192 * 64);
    const float* wl = w + (size_t)l * 3 * 4096;
    float v;
    if (kk < 64)       v = wl[kk * 64 + o] - wl[2 * 4096 + kk * 64 + o];
    else if (kk < 128) v = wl[4096 + (kk - 64) * 64 + o];
    else               v = 2.f * wl[2 * 4096 + (kk - 128) * 64 + o];
    g_weff[idx] = v;
}

// ---------------- warp-per-node CSR propagation (fp16 gather, fp32 accumulate) ----------------
// R13-proven structure; only the gathered feature rows are fp16 (halves LTS traffic).
__global__ void prop_warp_kernel(const __half2* __restrict__ h16, float* __restrict__ out,
                                 __half2* __restrict__ out16, int n) {
    int node = (blockIdx.x * blockDim.x + threadIdx.x) >> 5;
    if (node >= n) return;
    int lane = threadIdx.x & 31;
    int beg = g_rowptr[node];
    int end = g_rowptr[node + 1];
    float ax = 0.f, ay = 0.f;
    for (int j0 = beg; j0 < end; j0 += 32) {
        int jj = j0 + lane;
        int2 p = (jj < end) ? g_epay[jj] : make_int2(0, 0);
        int cnt = end - j0;
        if (cnt > 32) cnt = 32;
#pragma unroll 4
        for (int k = 0; k < cnt; k++) {
            int s   = __shfl_sync(0xffffffffu, p.x, k);
            float w = __int_as_float(__shfl_sync(0xffffffffu, p.y, k));
            float2 v = __half22float2(h16[(size_t)s * 32 + lane]);
            ax += w * v.x;
            ay += w * v.y;
        }
    }
    reinterpret_cast<float2*>(out)[(size_t)node * 32 + lane] = make_float2(ax, ay);
    if (out16) out16[(size_t)node * 32 + lane] = __floats2half2_rn(ax, ay);
}

// ---------------- tensor-core GEMM: out = [p0|p1|p2] @ Weff + bias (3xTF32) ----------------
// R13-proven version: static smem, hi/lo split in registers.
__device__ __forceinline__ uint32_t f2tf32(float x) {
    uint32_t r;
    asm("cvt.rna.tf32.f32 %0, %1;" : "=r"(r) : "f"(x));
    return r;
}

__device__ __forceinline__ void mma_tf32(float* d,
                                         uint32_t a0, uint32_t a1, uint32_t a2, uint32_t a3,
                                         uint32_t b0, uint32_t b1) {
    asm volatile("mma.sync.aligned.m16n8k8.row.col.f32.tf32.tf32.f32 "
                 "{%0,%1,%2,%3}, {%4,%5,%6,%7}, {%8,%9}, {%0,%1,%2,%3};"
                 : "+f"(d[0]), "+f"(d[1]), "+f"(d[2]), "+f"(d[3])
                 : "r"(a0), "r"(a1), "r"(a2), "r"(a3), "r"(b0), "r"(b1));
}

// BM=128, BN=64, K=192 (6 chunks of 32). 8 warps, 32x32 warp tiles.
// SMEM strides 136/72 (=8 mod 32) -> conflict-free LDS for frag patterns.
__global__ void __launch_bounds__(256, 2)
gemm_tc_kernel(const float* __restrict__ p0, const float* __restrict__ p1,
               const float* __restrict__ p2, const float* __restrict__ W,
               const float* __restrict__ bias, float* __restrict__ out,
               __half2* __restrict__ out16, int N) {
    __shared__ float As[32][136];     // [k][row]
    __shared__ float Whi[32][72];     // [k][n]
    __shared__ float Wlo[32][72];
    int tid = threadIdx.x;
    int lane = tid & 31;
    int wid = tid >> 5;               // 0..7
    int warp_m = wid >> 1;            // 0..3
    int warp_n = wid & 1;             // 0..1
    int gid = lane >> 2;              // 0..7
    int tig = lane & 3;               // 0..3
    int m0 = blockIdx.x * 128;

    float acc[2][4][4];
#pragma unroll
    for (int mf = 0; mf < 2; mf++)
#pragma unroll
        for (int nf = 0; nf < 4; nf++)
#pragma unroll
            for (int q = 0; q < 4; q++) acc[mf][nf][q] = 0.f;

    const float* parts[3] = {p0, p1, p2};

#pragma unroll 1
    for (int c = 0; c < 6; c++) {
        const float* P = parts[c >> 1];
        int kbase = (c & 1) * 32;      // column offset within the part
        // stage A chunk: 128 rows x 32 k
#pragma unroll
        for (int i = 0; i < 4; i++) {
            int idx = i * 256 + tid;
            int row = idx & 127;
            int kq = idx >> 7;         // 0..7
            int grow = m0 + row;
            float4 v = make_float4(0.f, 0.f, 0.f, 0.f);
            if (grow < N)
                v = *reinterpret_cast<const float4*>(P + (size_t)grow * 64 + kbase + kq * 4);
            As[kq * 4 + 0][row] = v.x;
            As[kq * 4 + 1][row] = v.y;
            As[kq * 4 + 2][row] = v.z;
            As[kq * 4 + 3][row] = v.w;
        }
        // stage W chunk (32 k-rows x 64 n) split into tf32 hi/lo
#pragma unroll
        for (int i = 0; i < 8; i++) {
            int idx = i * 256 + tid;
            int k = idx >> 6;          // 0..31
            int n = idx & 63;
            float w = W[(size_t)(c * 32 + k) * 64 + n];
            uint32_t hb = f2tf32(w);
            float lof = w - __uint_as_float(hb);
            Whi[k][n] = __uint_as_float(hb);
            Wlo[k][n] = __uint_as_float(f2tf32(lof));
        }
        __syncthreads();

#pragma unroll
        for (int ks = 0; ks < 4; ks++) {
            int k0 = ks * 8;
            uint32_t bh[4][2], bl[4][2];
#pragma unroll
            for (int nf = 0; nf < 4; nf++) {
                int col = warp_n * 32 + nf * 8 + gid;
                bh[nf][0] = __float_as_uint(Whi[k0 + tig][col]);
                bh[nf][1] = __float_as_uint(Whi[k0 + tig + 4][col]);
                bl[nf][0] = __float_as_uint(Wlo[k0 + tig][col]);
                bl[nf][1] = __float_as_uint(Wlo[k0 + tig + 4][col]);
            }
            uint32_t ah[2][4], al[2][4];
#pragma unroll
            for (int mf = 0; mf < 2; mf++) {
                int rb = warp_m * 32 + mf * 16;
                float a0 = As[k0 + tig][rb + gid];
                float a1 = As[k0 + tig][rb + gid + 8];
                float a2 = As[k0 + tig + 4][rb + gid];
                float a3 = As[k0 + tig + 4][rb + gid + 8];
                // PTX m16n8k8 A frag: a0=A[g][t], a1=A[g+8][t], a2=A[g][t+4], a3=A[g+8][t+4]
                float av[4] = {a0, a1, a2, a3};
#pragma unroll
                for (int q = 0; q < 4; q++) {
                    uint32_t hb = f2tf32(av[q]);
                    ah[mf][q] = hb;
                    al[mf][q] = f2tf32(av[q] - __uint_as_float(hb));
                }
            }
#pragma unroll
            for (int mf = 0; mf < 2; mf++)
#pragma unroll
                for (int nf = 0; nf < 4; nf++) {
                    mma_tf32(acc[mf][nf], ah[mf][0], ah[mf][1], ah[mf][2], ah[mf][3],
                             bh[nf][0], bh[nf][1]);
                    mma_tf32(acc[mf][nf], ah[mf][0], ah[mf][1], ah[mf][2], ah[mf][3],
                             bl[nf][0], bl[nf][1]);
                    mma_tf32(acc[mf][nf], al[mf][0], al[mf][1], al[mf][2], al[mf][3],
                             bh[nf][0], bh[nf][1]);
                }
        }
        __syncthreads();
    }

    // epilogue: bias + store fp32 (+ fp16 mirror for next layer's prop)
#pragma unroll
    for (int mf = 0; mf < 2; mf++) {
#pragma unroll
        for (int nf = 0; nf < 4; nf++) {
            int col = warp_n * 32 + nf * 8 + 2 * tig;
            float b0 = bias[col], b1 = bias[col + 1];
            int row0 = m0 + warp_m * 32 + mf * 16 + gid;
            if (row0 < N) {
                float2 o = make_float2(acc[mf][nf][0] + b0, acc[mf][nf][1] + b1);
                *reinterpret_cast<float2*>(out + (size_t)row0 * 64 + col) = o;
                if (out16) out16[(size_t)row0 * 32 + (col >> 1)] = __floats2half2_rn(o.x, o.y);
            }
            int row1 = row0 + 8;
            if (row1 < N) {
                float2 o = make_float2(acc[mf][nf][2] + b0, acc[mf][nf][3] + b1);
                *reinterpret_cast<float2*>(out + (size_t)row1 * 64 + col) = o;
                if (out16) out16[(size_t)row1 * 32 + (col >> 1)] = __floats2half2_rn(o.x, o.y);
            }
        }
    }
}

// ---------------- readout MLP (64->32 relu ->1) + scatter mean ----------------
__global__ void readout_kernel(const float* __restrict__ y, const int* __restrict__ batch,
                               const float* __restrict__ wr1, const float* __restrict__ br1,
                               const float* __restrict__ wr2, const float* __restrict__ br2,
                               int n, int G) {
    __shared__ float Wsm[64 * 32];
    __shared__ float w2sm[32];
    __shared__ float b1sm[32];
    for (int i = threadIdx.x; i < 64 * 32; i += blockDim.x) Wsm[i] = wr1[i];
    if (threadIdx.x < 32) {
        w2sm[threadIdx.x] = wr2[threadIdx.x];
        b1sm[threadIdx.x] = br1[threadIdx.x];
    }
    __syncthreads();
    float b2 = br2[0];
    int lane = threadIdx.x & 31;
    int warp = (blockIdx.x * blockDim.x + threadIdx.x) >> 5;
    int nwarps = (gridDim.x * blockDim.x) >> 5;
    for (int node = warp; node < n; node += nwarps) {
        float yv0 = y[(size_t)node * 64 + lane];
        float yv1 = y[(size_t)node * 64 + 32 + lane];
        float acc = b1sm[lane];
#pragma unroll
        for (int k = 0; k < 32; k++)
            acc += __shfl_sync(0xffffffffu, yv0, k) * Wsm[k * 32 + lane];
#pragma unroll
        for (int k = 0; k < 32; k++)
            acc += __shfl_sync(0xffffffffu, yv1, k) * Wsm[(32 + k) * 32 + lane];
        acc = fmaxf(acc, 0.f);
        float r = acc * w2sm[lane];
#pragma unroll
        for (int off = 16; off; off >>= 1)
            r += __shfl_xor_sync(0xffffffffu, r, off);
        if (lane == 0) {
            int g = batch[node];
            if ((unsigned)g < (unsigned)G) {
                atomicAdd(&g_sums[g], r + b2);
                atomicAdd(&g_cnt[g], 1.f);
            }
        }
    }
}

__global__ void finalize_kernel(float* __restrict__ out, int G) {
    int g = threadIdx.x;
    if (g < G) out[g] = g_sums[g] / fmaxf(g_cnt[g], 1.f);
}

// ---------------- host ----------------
extern "C" void kernel_launch(void* const* d_in, const int* in_sizes, int n_in,
                              void* d_out, int out_size) {
    const float* x        = (const float*)d_in[0];
    const int*   ei       = (const int*)d_in[1];     // int32 (JAX x64 disabled)
    const float* ew       = (const float*)d_in[2];
    const int*   batch    = (const int*)d_in[3];     // int32
    const float* w_layers = (const float*)d_in[4];
    const float* b_layers = (const float*)d_in[5];
    const float* wr1      = (const float*)d_in[6];
    const float* br1      = (const float*)d_in[7];
    const float* wr2      = (const float*)d_in[8];
    const float* br2      = (const float*)d_in[9];

    int N = in_sizes[0] / HDIM;
    int E = in_sizes[1] / 2;
    int G = out_size;

    float *bufA, *bufB, *tx1, *tmp, *weff;
    __half2 *hy16, *ht16;
    cudaGetSymbolAddress((void**)&bufA, g_bufA);
    cudaGetSymbolAddress((void**)&bufB, g_bufB);
    cudaGetSymbolAddress((void**)&tx1,  g_tx1);
    cudaGetSymbolAddress((void**)&tmp,  g_tmp);
    cudaGetSymbolAddress((void**)&weff, g_weff);
    cudaGetSymbolAddress((void**)&hy16, g_hy16);
    cudaGetSymbolAddress((void**)&ht16, g_ht16);

    const int TPB = 256;
    int nb = (N + 1023) / 1024;

    // preprocessing: degrees + CSR by target + Weff (+ pool zero) + x fp16 mirror
    init_counts_kernel<<<(N + TPB - 1) / TPB, TPB>>>(N);
    edge_prep_kernel<<<(E + TPB - 1) / TPB, TPB>>>(ei, ew, E, N);
    scan_block_kernel<<<nb, 1024>>>(N);
    scan_bsum_kernel<<<1, 128>>>(nb);
    scan_add_kernel<<<nb, 1024>>>(N, E);
    fill_kernel<<<(E + TPB - 1) / TPB, TPB>>>(ew, E);
    weff_kernel<<<(4 * 192 * 64 + TPB - 1) / TPB, TPB>>>(w_layers);
    cvt16_kernel<<<(N * 32 + TPB - 1) / TPB, TPB>>>(x, hy16, N * 32);

    int pgrid = (int)(((long long)N * 32 + TPB - 1) / TPB);
    int ggrid = (N + 127) / 128;

    const float* ycur = x;
    float* bufs[2] = {bufA, bufB};
    for (int l = 0; l < 4; l++) {
        // tx1 = P(y)  (fp16 gather; fp32 out + fp16 mirror for next prop)
        prop_warp_kernel<<<pgrid, TPB>>>(hy16, tx1, ht16, N);
        // tmp = P(tx1)
        prop_warp_kernel<<<pgrid, TPB>>>(ht16, tmp, nullptr, N);
        // y' = [y|tx1|tmp] @ Weff + b  (fp32; writes fp16 mirror of y' except last layer)
        gemm_tc_kernel<<<ggrid, TPB>>>(ycur, tx1, tmp,
                                       weff + (size_t)l * 192 * 64,
                                       b_layers + (size_t)l * 64,
                                       bufs[l & 1], (l < 3) ? hy16 : nullptr, N);
        ycur = bufs[l & 1];
    }

    // readout + pooling
    readout_kernel<<<256, TPB>>>(ycur, batch, wr1, br1, wr2, br2, N, G);
    finalize_kernel<<<1, 64>>>((float*)d_out, G);
}

// round 17
// speedup vs baseline: 1.0829x; 1.0163x over previous
#include <cuda_runtime.h>
#include <cstdint>

// ---------------- static scratch (device globals: allocation-free) ----------------
#define NMAX 100000
#define EMAX 1600000
#define HDIM 64

__device__ float g_deg[NMAX];
__device__ float g_dis[NMAX];
__device__ int   g_src[EMAX];
__device__ int   g_tgt[EMAX];
__device__ int   g_rowcnt[NMAX];
__device__ int   g_rowptr[NMAX + 1];
__device__ int   g_cursor[NMAX];
__device__ int   g_bsum[128];
__device__ int   g_bsumoff[128];
__device__ int2  g_epay[EMAX];          // {src, bits(wn)} grouped by tgt
__device__ float g_bufA[(size_t)NMAX * HDIM];
__device__ float g_bufB[(size_t)NMAX * HDIM];
__device__ float g_tx1[(size_t)NMAX * HDIM];
__device__ float g_tmp[(size_t)NMAX * HDIM];
__device__ float g_weff[4 * 192 * 64];
__device__ float g_sums[64];
__device__ float g_cnt[64];

// ---------------- utility ----------------
__global__ void init_counts_kernel(int n) {
    int i = blockIdx.x * blockDim.x + threadIdx.x;
    if (i < n) { g_deg[i] = 0.f; g_rowcnt[i] = 0; }
}

// ---------------- preprocessing ----------------
__global__ void edge_prep_kernel(const int* __restrict__ ei,
                                 const float* __restrict__ ew, int E, int N) {
    int e = blockIdx.x * blockDim.x + threadIdx.x;
    if (e >= E) return;
    int s = ei[e];
    int t = ei[(size_t)E + e];
    if ((unsigned)s >= (unsigned)N) s = 0;
    if ((unsigned)t >= (unsigned)N) t = 0;
    g_src[e] = s;
    g_tgt[e] = t;
    atomicAdd(&g_deg[s], ew[e]);
    atomicAdd(&g_rowcnt[t], 1);
}

// ---- multi-block exclusive scan of g_rowcnt -> g_rowptr (+ dis fused) ----
__global__ void scan_block_kernel(int N) {
    __shared__ int wsum[32];
    int tid = threadIdx.x, lane = tid & 31, wid = tid >> 5;
    int i = blockIdx.x * 1024 + tid;
    if (i < N) {
        float d = g_deg[i];
        g_dis[i] = (d > 0.f) ? rsqrtf(d) : 0.f;
    }
    int v = (i < N) ? g_rowcnt[i] : 0;
    int s = v;
#pragma unroll
    for (int o = 1; o < 32; o <<= 1) {
        int u = __shfl_up_sync(0xffffffffu, s, o);
        if (lane >= o) s += u;
    }
    if (lane == 31) wsum[wid] = s;
    __syncthreads();
    if (tid < 32) {
        int s2 = wsum[tid];
#pragma unroll
        for (int o = 1; o < 32; o <<= 1) {
            int u = __shfl_up_sync(0xffffffffu, s2, o);
            if (tid >= o) s2 += u;
        }
        wsum[tid] = s2;
    }
    __syncthreads();
    int excl = (wid ? wsum[wid - 1] : 0) + (s - v);
    if (i < N) g_rowptr[i] = excl;
    if (tid == 1023) g_bsum[blockIdx.x] = wsum[31];
}

__global__ void scan_bsum_kernel(int nb) {
    __shared__ int ws[4];
    int tid = threadIdx.x, lane = tid & 31, wid = tid >> 5;
    int v = (tid < nb) ? g_bsum[tid] : 0;
    int s = v;
#pragma unroll
    for (int o = 1; o < 32; o <<= 1) {
        int u = __shfl_up_sync(0xffffffffu, s, o);
        if (lane >= o) s += u;
    }
    if (lane == 31) ws[wid] = s;
    __syncthreads();
    if (tid == 0) { int a = 0; for (int w = 0; w < 4; w++) { int t = ws[w]; ws[w] = a; a += t; } }
    __syncthreads();
    int excl = ws[wid] + (s - v);
    if (tid < nb) g_bsumoff[tid] = excl;
}

__global__ void scan_add_kernel(int N, int E) {
    int i = blockIdx.x * 1024 + threadIdx.x;
    if (i < N) {
        int r = g_rowptr[i] + g_bsumoff[blockIdx.x];
        g_rowptr[i] = r;
        g_cursor[i] = r;
    }
    if (blockIdx.x == 0 && threadIdx.x == 0) g_rowptr[N] = E;
}

__global__ void fill_kernel(const float* __restrict__ ew, int E) {
    int e = blockIdx.x * blockDim.x + threadIdx.x;
    if (e >= E) return;
    int s = g_src[e];
    int t = g_tgt[e];
    float wn = -g_dis[s] * ew[e] * g_dis[t];
    int pos = atomicAdd(&g_cursor[t], 1);
    g_epay[pos] = make_int2(s, __float_as_int(wn));
}

// Weff[l][kk][o]: kk<64 -> W0-W2 ; 64..127 -> W1 ; 128..191 -> 2*W2
// (also zeroes the pooling accumulators: one launch fewer)
__global__ void weff_kernel(const float* __restrict__ w) {
    int idx = blockIdx.x * blockDim.x + threadIdx.x;
    if (blockIdx.x == 0) {
        if (threadIdx.x < 64) g_sums[threadIdx.x] = 0.f;
        else if (threadIdx.x < 128) g_cnt[threadIdx.x - 64] = 0.f;
    }
    if (idx >= 4 * 192 * 64) return;
    int o  = idx & 63;
    int kk = (idx >> 6) % 192;
    int l  = idx / (192 * 64);
    const float* wl = w + (size_t)l * 3 * 4096;
    float v;
    if (kk < 64)       v = wl[kk * 64 + o] - wl[2 * 4096 + kk * 64 + o];
    else if (kk < 128) v = wl[4096 + (kk - 64) * 64 + o];
    else               v = 2.f * wl[2 * 4096 + (kk - 128) * 64 + o];
    g_weff[idx] = v;
}

// ---------------- CSR propagation: 2 nodes/warp, 16 lanes/node, float4/lane ----------------
// Each half-warp owns one node: lane sub (0..15) holds 16B of the 256B row.
// Payloads batch-loaded 16 at a time, broadcast via width-16 shfl with a
// per-half mask (halves run independent trip counts -> disjoint masks are required).
__global__ void prop_warp_kernel(const float* __restrict__ h, float* __restrict__ out, int n) {
    int warp = (blockIdx.x * blockDim.x + threadIdx.x) >> 5;
    int lane = threadIdx.x & 31;
    int half = lane >> 4;            // 0 or 1
    int sub  = lane & 15;            // 0..15
    int node = warp * 2 + half;
    if (node >= n) return;
    unsigned hm = 0xFFFFu << (half << 4);
    int beg = g_rowptr[node];
    int end = g_rowptr[node + 1];
    const float4* __restrict__ hp = reinterpret_cast<const float4*>(h);
    float4 acc = make_float4(0.f, 0.f, 0.f, 0.f);
    for (int j0 = beg; j0 < end; j0 += 16) {
        int jj = j0 + sub;
        int2 p = (jj < end) ? g_epay[jj] : make_int2(0, 0);
        int cnt = end - j0;
        if (cnt > 16) cnt = 16;
#pragma unroll 4
        for (int k = 0; k < cnt; k++) {
            int s   = __shfl_sync(hm, p.x, k, 16);
            float w = __int_as_float(__shfl_sync(hm, p.y, k, 16));
            float4 v = hp[(size_t)s * 16 + sub];
            acc.x += w * v.x;
            acc.y += w * v.y;
            acc.z += w * v.z;
            acc.w += w * v.w;
        }
    }
    reinterpret_cast<float4*>(out)[(size_t)node * 16 + sub] = acc;
}

// ---------------- tensor-core GEMM: out = [p0|p1|p2] @ Weff + bias (3xTF32) ----------------
__device__ __forceinline__ uint32_t f2tf32(float x) {
    uint32_t r;
    asm("cvt.rna.tf32.f32 %0, %1;" : "=r"(r) : "f"(x));
    return r;
}

__device__ __forceinline__ void mma_tf32(float* d,
                                         uint32_t a0, uint32_t a1, uint32_t a2, uint32_t a3,
                                         uint32_t b0, uint32_t b1) {
    asm volatile("mma.sync.aligned.m16n8k8.row.col.f32.tf32.tf32.f32 "
                 "{%0,%1,%2,%3}, {%4,%5,%6,%7}, {%8,%9}, {%0,%1,%2,%3};"
                 : "+f"(d[0]), "+f"(d[1]), "+f"(d[2]), "+f"(d[3])
                 : "r"(a0), "r"(a1), "r"(a2), "r"(a3), "r"(b0), "r"(b1));
}

// BM=128, BN=64, K=192 (6 chunks of 32). 8 warps, 32x32 warp tiles.
// SMEM strides 136/72 (=8 mod 32) -> conflict-free LDS for frag patterns.
__global__ void __launch_bounds__(256, 2)
gemm_tc_kernel(const float* __restrict__ p0, const float* __restrict__ p1,
               const float* __restrict__ p2, const float* __restrict__ W,
               const float* __restrict__ bias, float* __restrict__ out, int N) {
    __shared__ float As[32][136];     // [k][row]
    __shared__ float Whi[32][72];     // [k][n]
    __shared__ float Wlo[32][72];
    int tid = threadIdx.x;
    int lane = tid & 31;
    int wid = tid >> 5;               // 0..7
    int warp_m = wid >> 1;            // 0..3
    int warp_n = wid & 1;             // 0..1
    int gid = lane >> 2;              // 0..7
    int tig = lane & 3;               // 0..3
    int m0 = blockIdx.x * 128;

    float acc[2][4][4];
#pragma unroll
    for (int mf = 0; mf < 2; mf++)
#pragma unroll
        for (int nf = 0; nf < 4; nf++)
#pragma unroll
            for (int q = 0; q < 4; q++) acc[mf][nf][q] = 0.f;

    const float* parts[3] = {p0, p1, p2};

#pragma unroll 1
    for (int c = 0; c < 6; c++) {
        const float* P = parts[c >> 1];
        int kbase = (c & 1) * 32;      // column offset within the part
        // stage A chunk: 128 rows x 32 k
#pragma unroll
        for (int i = 0; i < 4; i++) {
            int idx = i * 256 + tid;
            int row = idx & 127;
            int kq = idx >> 7;         // 0..7
            int grow = m0 + row;
            float4 v = make_float4(0.f, 0.f, 0.f, 0.f);
            if (grow < N)
                v = *reinterpret_cast<const float4*>(P + (size_t)grow * 64 + kbase + kq * 4);
            As[kq * 4 + 0][row] = v.x;
            As[kq * 4 + 1][row] = v.y;
            As[kq * 4 + 2][row] = v.z;
            As[kq * 4 + 3][row] = v.w;
        }
        // stage W chunk (32 k-rows x 64 n) split into tf32 hi/lo
#pragma unroll
        for (int i = 0; i < 8; i++) {
            int idx = i * 256 + tid;
            int k = idx >> 6;          // 0..31
            int n = idx & 63;
            float w = W[(size_t)(c * 32 + k) * 64 + n];
            uint32_t hb = f2tf32(w);
            float lof = w - __uint_as_float(hb);
            Whi[k][n] = __uint_as_float(hb);
            Wlo[k][n] = __uint_as_float(f2tf32(lof));
        }
        __syncthreads();

#pragma unroll
        for (int ks = 0; ks < 4; ks++) {
            int k0 = ks * 8;
            uint32_t bh[4][2], bl[4][2];
#pragma unroll
            for (int nf = 0; nf < 4; nf++) {
                int col = warp_n * 32 + nf * 8 + gid;
                bh[nf][0] = __float_as_uint(Whi[k0 + tig][col]);
                bh[nf][1] = __float_as_uint(Whi[k0 + tig + 4][col]);
                bl[nf][0] = __float_as_uint(Wlo[k0 + tig][col]);
                bl[nf][1] = __float_as_uint(Wlo[k0 + tig + 4][col]);
            }
            uint32_t ah[2][4], al[2][4];
#pragma unroll
            for (int mf = 0; mf < 2; mf++) {
                int rb = warp_m * 32 + mf * 16;
                float a0 = As[k0 + tig][rb + gid];
                float a1 = As[k0 + tig][rb + gid + 8];
                float a2 = As[k0 + tig + 4][rb + gid];
                float a3 = As[k0 + tig + 4][rb + gid + 8];
                // PTX m16n8k8 A frag: a0=A[g][t], a1=A[g+8][t], a2=A[g][t+4], a3=A[g+8][t+4]
                float av[4] = {a0, a1, a2, a3};
#pragma unroll
                for (int q = 0; q < 4; q++) {
                    uint32_t hb = f2tf32(av[q]);
                    ah[mf][q] = hb;
                    al[mf][q] = f2tf32(av[q] - __uint_as_float(hb));
                }
            }
#pragma unroll
            for (int mf = 0; mf < 2; mf++)
#pragma unroll
                for (int nf = 0; nf < 4; nf++) {
                    mma_tf32(acc[mf][nf], ah[mf][0], ah[mf][1], ah[mf][2], ah[mf][3],
                             bh[nf][0], bh[nf][1]);
                    mma_tf32(acc[mf][nf], ah[mf][0], ah[mf][1], ah[mf][2], ah[mf][3],
                             bl[nf][0], bl[nf][1]);
                    mma_tf32(acc[mf][nf], al[mf][0], al[mf][1], al[mf][2], al[mf][3],
                             bh[nf][0], bh[nf][1]);
                }
        }
        __syncthreads();
    }

    // epilogue: bias + store (C frag: c0=C[g][2t], c1=C[g][2t+1], c2=C[g+8][2t], c3=C[g+8][2t+1])
#pragma unroll
    for (int mf = 0; mf < 2; mf++) {
#pragma unroll
        for (int nf = 0; nf < 4; nf++) {
            int col = warp_n * 32 + nf * 8 + 2 * tig;
            float b0 = bias[col], b1 = bias[col + 1];
            int row0 = m0 + warp_m * 32 + mf * 16 + gid;
            if (row0 < N) {
                float2 o = make_float2(acc[mf][nf][0] + b0, acc[mf][nf][1] + b1);
                *reinterpret_cast<float2*>(out + (size_t)row0 * 64 + col) = o;
            }
            int row1 = row0 + 8;
            if (row1 < N) {
                float2 o = make_float2(acc[mf][nf][2] + b0, acc[mf][nf][3] + b1);
                *reinterpret_cast<float2*>(out + (size_t)row1 * 64 + col) = o;
            }
        }
    }
}

// ---------------- readout MLP (64->32 relu ->1) + scatter mean ----------------
__global__ void readout_kernel(const float* __restrict__ y, const int* __restrict__ batch,
                               const float* __restrict__ wr1, const float* __restrict__ br1,
                               const float* __restrict__ wr2, const float* __restrict__ br2,
                               int n, int G) {
    __shared__ float Wsm[64 * 32];
    __shared__ float w2sm[32];
    __shared__ float b1sm[32];
    for (int i = threadIdx.x; i < 64 * 32; i += blockDim.x) Wsm[i] = wr1[i];
    if (threadIdx.x < 32) {
        w2sm[threadIdx.x] = wr2[threadIdx.x];
        b1sm[threadIdx.x] = br1[threadIdx.x];
    }
    __syncthreads();
    float b2 = br2[0];
    int lane = threadIdx.x & 31;
    int warp = (blockIdx.x * blockDim.x + threadIdx.x) >> 5;
    int nwarps = (gridDim.x * blockDim.x) >> 5;
    for (int node = warp; node < n; node += nwarps) {
        float yv0 = y[(size_t)node * 64 + lane];
        float yv1 = y[(size_t)node * 64 + 32 + lane];
        float acc = b1sm[lane];
#pragma unroll
        for (int k = 0; k < 32; k++)
            acc += __shfl_sync(0xffffffffu, yv0, k) * Wsm[k * 32 + lane];
#pragma unroll
        for (int k = 0; k < 32; k++)
            acc += __shfl_sync(0xffffffffu, yv1, k) * Wsm[(32 + k) * 32 + lane];
        acc = fmaxf(acc, 0.f);
        float r = acc * w2sm[lane];
#pragma unroll
        for (int off = 16; off; off >>= 1)
            r += __shfl_xor_sync(0xffffffffu, r, off);
        if (lane == 0) {
            int g = batch[node];
            if ((unsigned)g < (unsigned)G) {
                atomicAdd(&g_sums[g], r + b2);
                atomicAdd(&g_cnt[g], 1.f);
            }
        }
    }
}

__global__ void finalize_kernel(float* __restrict__ out, int G) {
    int g = threadIdx.x;
    if (g < G) out[g] = g_sums[g] / fmaxf(g_cnt[g], 1.f);
}

// ---------------- host ----------------
extern "C" void kernel_launch(void* const* d_in, const int* in_sizes, int n_in,
                              void* d_out, int out_size) {
    const float* x        = (const float*)d_in[0];
    const int*   ei       = (const int*)d_in[1];     // int32 (JAX x64 disabled)
    const float* ew       = (const float*)d_in[2];
    const int*   batch    = (const int*)d_in[3];     // int32
    const float* w_layers = (const float*)d_in[4];
    const float* b_layers = (const float*)d_in[5];
    const float* wr1      = (const float*)d_in[6];
    const float* br1      = (const float*)d_in[7];
    const float* wr2      = (const float*)d_in[8];
    const float* br2      = (const float*)d_in[9];

    int N = in_sizes[0] / HDIM;
    int E = in_sizes[1] / 2;
    int G = out_size;

    float *bufA, *bufB, *tx1, *tmp, *weff;
    cudaGetSymbolAddress((void**)&bufA, g_bufA);
    cudaGetSymbolAddress((void**)&bufB, g_bufB);
    cudaGetSymbolAddress((void**)&tx1,  g_tx1);
    cudaGetSymbolAddress((void**)&tmp,  g_tmp);
    cudaGetSymbolAddress((void**)&weff, g_weff);

    const int TPB = 256;
    int nb = (N + 1023) / 1024;

    // preprocessing: degrees + CSR by target + Weff (+ pool zero)
    init_counts_kernel<<<(N + TPB - 1) / TPB, TPB>>>(N);
    edge_prep_kernel<<<(E + TPB - 1) / TPB, TPB>>>(ei, ew, E, N);
    scan_block_kernel<<<nb, 1024>>>(N);
    scan_bsum_kernel<<<1, 128>>>(nb);
    scan_add_kernel<<<nb, 1024>>>(N, E);
    fill_kernel<<<(E + TPB - 1) / TPB, TPB>>>(ew, E);
    weff_kernel<<<(4 * 192 * 64 + TPB - 1) / TPB, TPB>>>(w_layers);

    // 2 nodes per warp -> ceil(N/2) warps
    int pwarps = (N + 1) / 2;
    int pgrid = (int)(((long long)pwarps * 32 + TPB - 1) / TPB);
    int ggrid = (N + 127) / 128;

    const float* ycur = x;
    float* bufs[2] = {bufA, bufB};
    for (int l = 0; l < 4; l++) {
        prop_warp_kernel<<<pgrid, TPB>>>(ycur, tx1, N);
        prop_warp_kernel<<<pgrid, TPB>>>(tx1, tmp, N);
        gemm_tc_kernel<<<ggrid, TPB>>>(ycur, tx1, tmp,
                                       weff + (size_t)l * 192 * 64,
                                       b_layers + (size_t)l * 64,
                                       bufs[l & 1], N);
        ycur = bufs[l & 1];
    }

    // readout + pooling
    readout_kernel<<<256, TPB>>>(ycur, batch, wr1, br1, wr2, br2, N, G);
    finalize_kernel<<<1, 64>>>((float*)d_out, G);
}